// round 3
// baseline (speedup 1.0000x reference)
#include <cuda_runtime.h>
#include <math.h>

#define R_ 3
#define T_ 3
#define N_ 50000
#define OPS_ 24
#define E_ 400000
#define B_ 32
#define MAXDEG_ 8
#define QD_ 128
#define ED_ 128
#define H_ 128

// ---------------- scratch (device globals; no allocations allowed) ----------------
__device__ float g_xgI[2 * 25 * 512];        // xg interleaved [dir][d][j*4+g]
__device__ float g_WhhI[2 * 128 * 512];      // Whh interleaved [dir][k][j*4+g]
__device__ float g_eh[N_ * 256];             // entity BiLSTM final hidden (N, 2H)
__device__ float g_attn[N_ * OPS_];          // entity attention (N, 24)
__device__ float g_w[E_];                    // per-edge weight
__device__ float g_qys[R_ * 2 * T_ * B_ * H_];
__device__ float g_qaT[R_ * T_ * (OPS_ + 1) * B_];   // [rt][op][b]
__device__ float g_mem[N_ * B_];             // memory, layout (N, B)
__device__ float g_added[N_ * B_];
__device__ float g_gsum[B_];

__device__ __forceinline__ float sigm(float x) { return 1.f / (1.f + expf(-x)); }

// ---------------- precompute: xg[dir][d][j*4+g] = emb[d]@Wih^T + bih + bhh -------
__global__ void k_xg(const float* __restrict__ ent_emb, const float* __restrict__ e_Wih,
                     const float* __restrict__ e_bih, const float* __restrict__ e_bhh) {
    int d = blockIdx.x, dir = blockIdx.y, tid = threadIdx.x;  // 512 threads
    int j = tid >> 2, g = tid & 3;
    int row = g * 128 + j;
    const float* w = e_Wih + (dir * 512 + row) * 128;
    const float* x = ent_emb + d * 128;
    float s = e_bih[dir * 512 + row] + e_bhh[dir * 512 + row];
    for (int k = 0; k < 128; k++) s += x[k] * w[k];
    g_xgI[(dir * 25 + d) * 512 + tid] = s;
}

// ---------------- precompute: WhhI[dir][k][j*4+g] = Whh[dir][g*128+j][k] ---------
__global__ void k_whhT(const float* __restrict__ e_Whh) {
    int k = blockIdx.x, dir = blockIdx.y, tid = threadIdx.x;  // 512 threads
    int j = tid >> 2, g = tid & 3;
    g_WhhI[(dir * 128 + k) * 512 + tid] = e_Whh[(dir * 512 + g * 128 + j) * 128 + k];
}

// ---------------- entity BiLSTM: the heavy kernel --------------------------------
#define EK_THREADS 512
#define TILE_M 32
#define SH_PITCH 36

__global__ void __launch_bounds__(EK_THREADS) k_entity(const int* __restrict__ degrees) {
    extern __shared__ float smem[];
    float* sB = smem;                              // 2 * 16 * 512 floats (double buffer)
    float* sh = smem + 2 * 16 * 512;               // hT: [128][36] padded
    int* sdeg = (int*)(sh + 128 * SH_PITCH);       // [32][8]

    int dir = blockIdx.y;
    int n0 = blockIdx.x * TILE_M;
    int tid = threadIdx.x;

    if (tid < TILE_M * MAXDEG_) {
        int m = tid >> 3, t = tid & 7;
        int n = n0 + m;
        int d = (n < N_) ? degrees[n * MAXDEG_ + (dir ? (MAXDEG_ - 1 - t) : t)] : OPS_;
        sdeg[m * MAXDEG_ + t] = d;
    }
    for (int i = tid; i < 128 * SH_PITCH; i += EK_THREADS) sh[i] = 0.f;

    int jp = tid & 63;   // 0..63 -> hidden unit pair
    int mg = tid >> 6;   // 0..7  -> entity group of 4
    int j0 = jp << 1;
    int m0 = mg << 2;

    float c[8], hn[8];
#pragma unroll
    for (int i = 0; i < 8; i++) { c[i] = 0.f; hn[i] = 0.f; }

    const float4* Wd4 = (const float4*)(g_WhhI + dir * 128 * 512);
    const float* xd = g_xgI + dir * 25 * 512;
    __syncthreads();

    float4 pre[4];
    for (int step = 0; step < MAXDEG_; step++) {
        float acc[4][8];
#pragma unroll
        for (int m = 0; m < 4; m++)
#pragma unroll
            for (int q = 0; q < 8; q++) acc[m][q] = 0.f;

        // stage chunk 0 (16 k-rows of WhhI)
#pragma unroll
        for (int p = 0; p < 4; p++) pre[p] = Wd4[p * 512 + tid];
#pragma unroll
        for (int p = 0; p < 4; p++) ((float4*)sB)[p * 512 + tid] = pre[p];
        __syncthreads();

        for (int chunk = 0; chunk < 8; chunk++) {
            const float* buf = sB + (chunk & 1) * 8192;
            if (chunk < 7) {
#pragma unroll
                for (int p = 0; p < 4; p++)
                    pre[p] = Wd4[(chunk + 1) * 2048 + p * 512 + tid];
            }
#pragma unroll
            for (int kk = 0; kk < 16; kk++) {
                int k = chunk * 16 + kk;
                float4 a  = *(const float4*)&sh[k * SH_PITCH + m0];
                float4 b0 = *(const float4*)&buf[kk * 512 + j0 * 4];
                float4 b1 = *(const float4*)&buf[kk * 512 + j0 * 4 + 4];
                float aa[4] = {a.x, a.y, a.z, a.w};
                float bb[8] = {b0.x, b0.y, b0.z, b0.w, b1.x, b1.y, b1.z, b1.w};
#pragma unroll
                for (int m = 0; m < 4; m++)
#pragma unroll
                    for (int q = 0; q < 8; q++) acc[m][q] += aa[m] * bb[q];
            }
            __syncthreads();
            if (chunk < 7) {
                float* nb = sB + ((chunk + 1) & 1) * 8192;
#pragma unroll
                for (int p = 0; p < 4; p++) ((float4*)nb)[p * 512 + tid] = pre[p];
                __syncthreads();
            }
        }

        // gate nonlinearities (per-thread private c)
#pragma unroll
        for (int m = 0; m < 4; m++) {
            int d = sdeg[(m0 + m) * MAXDEG_ + step];
            const float4* xb = (const float4*)&xd[d * 512 + j0 * 4];
#pragma unroll
            for (int jj = 0; jj < 2; jj++) {
                float4 xv = xb[jj];
                float iv = acc[m][jj * 4 + 0] + xv.x;
                float fv = acc[m][jj * 4 + 1] + xv.y;
                float gv = acc[m][jj * 4 + 2] + xv.z;
                float ov = acc[m][jj * 4 + 3] + xv.w;
                int ci = m * 2 + jj;
                c[ci] = sigm(fv) * c[ci] + sigm(iv) * tanhf(gv);
                hn[ci] = sigm(ov) * tanhf(c[ci]);
            }
        }
        // all reads of old h finished (barrier after last chunk); publish new h
#pragma unroll
        for (int m = 0; m < 4; m++) {
            sh[j0 * SH_PITCH + m0 + m]       = hn[m * 2 + 0];
            sh[(j0 + 1) * SH_PITCH + m0 + m] = hn[m * 2 + 1];
        }
        __syncthreads();
    }

    // write final hidden state (only thing needed downstream)
#pragma unroll
    for (int m = 0; m < 4; m++) {
        int n = n0 + m0 + m;
        if (n < N_) {
            g_eh[n * 256 + dir * 128 + j0]     = hn[m * 2 + 0];
            g_eh[n * 256 + dir * 128 + j0 + 1] = hn[m * 2 + 1];
        }
    }
}

// ---------------- entity attention softmax: warp per entity ----------------------
__global__ void k_eattn(const float* __restrict__ e_lin_W, const float* __restrict__ e_lin_b) {
    int warp = (blockIdx.x * blockDim.x + threadIdx.x) >> 5;
    int lane = threadIdx.x & 31;
    if (warp >= N_) return;
    int n = warp;
    float s = -1e30f;
    if (lane < OPS_) {
        s = e_lin_b[lane];
        const float4* h4 = (const float4*)(g_eh + n * 256);
        const float4* w4 = (const float4*)(e_lin_W + lane * 256);
#pragma unroll 4
        for (int k = 0; k < 64; k++) {
            float4 hh = h4[k], ww = w4[k];
            s += hh.x * ww.x + hh.y * ww.y + hh.z * ww.z + hh.w * ww.w;
        }
    }
    float mx = s;
    for (int o = 16; o; o >>= 1) mx = fmaxf(mx, __shfl_xor_sync(0xffffffffu, mx, o));
    float e = (lane < OPS_) ? expf(s - mx) : 0.f;
    float sum = e;
    for (int o = 16; o; o >>= 1) sum += __shfl_xor_sync(0xffffffffu, sum, o);
    if (lane < OPS_) g_attn[n * OPS_ + lane] = e / sum;
}

// ---------------- per-edge weight gather -----------------------------------------
__global__ void k_w(const int* __restrict__ rels, const int* __restrict__ t_heads) {
    int e = blockIdx.x * blockDim.x + threadIdx.x;
    if (e < E_) g_w[e] = g_attn[t_heads[e] * OPS_ + rels[e]];
}

// ---------------- query BiLSTM: one warp per (r, dir, b) -------------------------
__global__ void k_qlstm(const int* __restrict__ queries, const float* __restrict__ q_emb,
                        const float* __restrict__ q_Wih, const float* __restrict__ q_Whh,
                        const float* __restrict__ q_bih, const float* __restrict__ q_bhh) {
    int w = (blockIdx.x * blockDim.x + threadIdx.x) >> 5;
    int lane = threadIdx.x & 31;
    if (w >= R_ * 2 * B_) return;
    int b = w & 31;
    int dir = (w >> 5) & 1;
    int r = w >> 6;
    int rd = r * 2 + dir;

    const float* x = q_emb + queries[b] * QD_;
    const float* Wih = q_Wih + rd * 512 * 128;
    const float* Whh = q_Whh + rd * 512 * 128;
    const float* bih = q_bih + rd * 512;
    const float* bhh = q_bhh + rd * 512;

    float xw[4][4];
#pragma unroll
    for (int g = 0; g < 4; g++)
#pragma unroll
        for (int s = 0; s < 4; s++) {
            int row = g * 128 + lane + 32 * s;
            float acc = bih[row] + bhh[row];
            const float* wr = Wih + row * 128;
            for (int k = 0; k < 128; k++) acc += x[k] * wr[k];
            xw[g][s] = acc;
        }

    float h[4] = {0, 0, 0, 0}, c4[4] = {0, 0, 0, 0};
    for (int t = 0; t < T_; t++) {
        float gg[4][4];
#pragma unroll
        for (int g = 0; g < 4; g++)
#pragma unroll
            for (int s = 0; s < 4; s++) gg[g][s] = xw[g][s];
        for (int k = 0; k < 128; k++) {
            float hk = __shfl_sync(0xffffffffu, h[k >> 5], k & 31);
#pragma unroll
            for (int g = 0; g < 4; g++)
#pragma unroll
                for (int s = 0; s < 4; s++)
                    gg[g][s] += hk * Whh[(g * 128 + lane + 32 * s) * 128 + k];
        }
#pragma unroll
        for (int s = 0; s < 4; s++) {
            float iv = gg[0][s], fv = gg[1][s], gv = gg[2][s], ov = gg[3][s];
            c4[s] = sigm(fv) * c4[s] + sigm(iv) * tanhf(gv);
            h[s] = sigm(ov) * tanhf(c4[s]);
        }
#pragma unroll
        for (int s = 0; s < 4; s++)
            g_qys[((rd * 3 + t) * B_ + b) * H_ + lane + 32 * s] = h[s];
    }
}

// ---------------- query attention softmax: warp per (r,t,b) ----------------------
__global__ void k_qattn(const float* __restrict__ q_lin_W, const float* __restrict__ q_lin_b) {
    int w = (blockIdx.x * blockDim.x + threadIdx.x) >> 5;
    int lane = threadIdx.x & 31;
    if (w >= R_ * T_ * B_) return;
    int b = w & 31;
    int t = (w >> 5) % 3;
    int r = w / (3 * 32);
    const float* ysf = g_qys + (((r * 2 + 0) * 3 + t) * B_ + b) * H_;
    const float* ysb = g_qys + (((r * 2 + 1) * 3 + (2 - t)) * B_ + b) * H_;
    float s = -1e30f;
    if (lane <= OPS_) {  // 25 lanes active
        s = q_lin_b[lane];
        const float* wv = q_lin_W + lane * 256;
        for (int k = 0; k < 128; k++) s += ysf[k] * wv[k];
        for (int k = 0; k < 128; k++) s += ysb[k] * wv[128 + k];
    }
    float mx = s;
    for (int o = 16; o; o >>= 1) mx = fmaxf(mx, __shfl_xor_sync(0xffffffffu, mx, o));
    float e = (lane <= OPS_) ? expf(s - mx) : 0.f;
    float sum = e;
    for (int o = 16; o; o >>= 1) sum += __shfl_xor_sync(0xffffffffu, sum, o);
    if (lane <= OPS_)
        g_qaT[((r * 3 + t) * (OPS_ + 1) + lane) * B_ + b] = e / sum;
}

// ---------------- propagation kernels --------------------------------------------
__global__ void k_seed(const int* __restrict__ heads) {
    int b = threadIdx.x;
    if (b < B_) g_mem[heads[b] * B_ + b] = 1.f;
}

__global__ void k_edge(const int* __restrict__ rels, const int* __restrict__ t_heads,
                       const int* __restrict__ t_tails, int rt) {
    __shared__ float qs[(OPS_ + 1) * B_];
    int tid = threadIdx.x;
    const float* qsrc = g_qaT + rt * (OPS_ + 1) * B_;
    for (int i = tid; i < (OPS_ + 1) * B_; i += blockDim.x) qs[i] = qsrc[i];
    __syncthreads();
    int lane = tid & 31;
    int warp = (blockIdx.x * blockDim.x + tid) >> 5;
    int nw = (gridDim.x * blockDim.x) >> 5;
    for (int e = warp; e < E_; e += nw) {
        int rel = rels[e], hd = t_heads[e], tl = t_tails[e];
        float we = g_w[e];
        float fwd = qs[rel * B_ + lane] * we * g_mem[hd * B_ + lane];
        float rev = qs[(rel + OPS_ / 2) * B_ + lane] * we * g_mem[tl * B_ + lane];
        atomicAdd(&g_added[tl * B_ + lane], fwd);
        atomicAdd(&g_added[hd * B_ + lane], rev);
    }
}

__global__ void k_self(int rt) {
    __shared__ float red[8][32];
    int tid = threadIdx.x;
    int lane = tid & 31, rg = tid >> 5;
    float qlast = g_qaT[(rt * (OPS_ + 1) + OPS_) * B_ + lane];
    float local = 0.f;
    for (int n = blockIdx.x * 8 + rg; n < N_; n += gridDim.x * 8) {
        int i = n * B_ + lane;
        float v = g_added[i] + g_mem[i] * qlast;
        g_added[i] = v;
        local += v;
    }
    red[rg][lane] = local;
    __syncthreads();
    if (rg == 0) {
        float s = 0.f;
#pragma unroll
        for (int q = 0; q < 8; q++) s += red[q][lane];
        atomicAdd(&g_gsum[lane], s);
    }
}

__global__ void k_norm() {
    int i = blockIdx.x * blockDim.x + threadIdx.x;
    if (i < N_ * B_) {
        float d = g_gsum[i & 31];
        g_mem[i] = g_added[i] / fmaxf(1e-20f, d);
    }
}

__global__ void k_accum(float* __restrict__ out) {
    int i = blockIdx.x * blockDim.x + threadIdx.x;
    if (i < N_ * B_) {
        int b = i / N_;
        int n = i - b * N_;
        out[i] += g_mem[n * B_ + b];
    }
}

// ---------------- host launch ----------------------------------------------------
extern "C" void kernel_launch(void* const* d_in, const int* in_sizes, int n_in,
                              void* d_out, int out_size) {
    const int* queries   = (const int*)d_in[0];
    const int* heads     = (const int*)d_in[1];
    const int* rels      = (const int*)d_in[2];
    const int* t_heads   = (const int*)d_in[3];
    const int* t_tails   = (const int*)d_in[4];
    const int* degrees   = (const int*)d_in[5];
    const float* q_emb   = (const float*)d_in[6];
    const float* ent_emb = (const float*)d_in[7];
    const float* q_Wih   = (const float*)d_in[8];
    const float* q_Whh   = (const float*)d_in[9];
    const float* q_bih   = (const float*)d_in[10];
    const float* q_bhh   = (const float*)d_in[11];
    const float* e_Wih   = (const float*)d_in[12];
    const float* e_Whh   = (const float*)d_in[13];
    const float* e_bih   = (const float*)d_in[14];
    const float* e_bhh   = (const float*)d_in[15];
    const float* q_lin_W = (const float*)d_in[16];
    const float* q_lin_b = (const float*)d_in[17];
    const float* e_lin_W = (const float*)d_in[18];
    const float* e_lin_b = (const float*)d_in[19];
    float* out = (float*)d_out;

    void *p_mem, *p_added, *p_gsum;
    cudaGetSymbolAddress(&p_mem, g_mem);
    cudaGetSymbolAddress(&p_added, g_added);
    cudaGetSymbolAddress(&p_gsum, g_gsum);

    cudaMemsetAsync(d_out, 0, (size_t)N_ * B_ * sizeof(float));

    // precompute
    k_xg<<<dim3(25, 2), 512>>>(ent_emb, e_Wih, e_bih, e_bhh);
    k_whhT<<<dim3(128, 2), 512>>>(e_Whh);

    // entity BiLSTM (dominant)
    size_t smem = (size_t)(2 * 16 * 512 + 128 * SH_PITCH) * sizeof(float) +
                  (size_t)TILE_M * MAXDEG_ * sizeof(int);
    cudaFuncSetAttribute(k_entity, cudaFuncAttributeMaxDynamicSharedMemorySize, (int)smem);
    k_entity<<<dim3((N_ + TILE_M - 1) / TILE_M, 2), EK_THREADS, smem>>>(degrees);

    k_eattn<<<(N_ * 32 + 255) / 256, 256>>>(e_lin_W, e_lin_b);
    k_w<<<(E_ + 255) / 256, 256>>>(rels, t_heads);

    // query path
    k_qlstm<<<24, 256>>>(queries, q_emb, q_Wih, q_Whh, q_bih, q_bhh);
    k_qattn<<<36, 256>>>(q_lin_W, q_lin_b);

    // propagation
    for (int r = 0; r < R_; r++) {
        cudaMemsetAsync(p_mem, 0, (size_t)N_ * B_ * sizeof(float));
        k_seed<<<1, 32>>>(heads);
        for (int t = 0; t < T_; t++) {
            int rt = r * 3 + t;
            cudaMemsetAsync(p_added, 0, (size_t)N_ * B_ * sizeof(float));
            cudaMemsetAsync(p_gsum, 0, B_ * sizeof(float));
            k_edge<<<2048, 256>>>(rels, t_heads, t_tails, rt);
            k_self<<<256, 256>>>(rt);
            k_norm<<<(N_ * B_ + 255) / 256, 256>>>();
        }
        k_accum<<<(N_ * B_ + 255) / 256, 256>>>(out);
    }
}